// round 13
// baseline (speedup 1.0000x reference)
#include <cuda_runtime.h>
#include <cuda_bf16.h>

#define NLAY 256
#define TSTEPS 64
#define BATCH 4
#define HDIM 256
#define GDIM 768
#define NCLS 26

// Sequence slots: enc layer l reads g_seq[l], writes g_seq[l+1] (slot 256 = relu'd emb).
// dec layer d reads g_seq[256] (d==0) else g_seq[d-1], writes g_seq[d].
__device__ float g_seq[NLAY + 1][TSTEPS][BATCH][HDIM];
// One flag per quarter-block: g_flags[pairIdx*4 + q], pairIdx 0..511.
__device__ int g_flags[4 * 2 * NLAY];

typedef unsigned long long u64;

__device__ __forceinline__ void unpk2(u64 v, float& lo, float& hi) {
    asm("mov.b64 {%0,%1},%2;" : "=f"(lo), "=f"(hi) : "l"(v));
}
__device__ __forceinline__ u64 expand_bf2(unsigned u) {
    float lo = __uint_as_float(u << 16);
    float hi = __uint_as_float(u & 0xffff0000u);
    u64 r; asm("mov.b64 %0,{%1,%2};" : "=l"(r) : "f"(lo), "f"(hi)); return r;
}
__device__ __forceinline__ void fma2(u64& acc, u64 a, u64 b) {
    asm("fma.rn.f32x2 %0,%1,%2,%0;" : "+l"(acc) : "l"(a), "l"(b));
}
__device__ __forceinline__ float sigm(float x) { return 1.f / (1.f + __expf(-x)); }
__device__ __forceinline__ unsigned packbf(float f0, float f1) {
    return (unsigned)__bfloat16_as_ushort(__float2bfloat16(f0)) |
           ((unsigned)__bfloat16_as_ushort(__float2bfloat16(f1)) << 16);
}

__global__ void zero_flags_kernel() {
    int i = blockIdx.x * blockDim.x + threadIdx.x;
    if (i < 4 * 2 * NLAY) g_flags[i] = 0;
}

// Pointwise convs collapse: seq[0][t][b][h] = X[b,0,2t]*A[h] + C[h]
__global__ void conv_front_kernel(const float* __restrict__ X,
                                  const float* __restrict__ c1w,
                                  const float* __restrict__ c1b,
                                  const float* __restrict__ c2w,
                                  const float* __restrict__ c2b) {
    __shared__ float xs[512];
    int j = threadIdx.x;
    xs[j] = X[j];
    xs[256 + j] = X[256 + j];
    __syncthreads();
    float A = 0.f, C = 0.f;
    for (int c = 0; c < 128; ++c) {
        float w2 = c2w[j * 128 + c];
        A += w2 * c1w[c];
        C += w2 * c1b[c];
    }
    C += c2b[j];
    for (int t = 0; t < TSTEPS; ++t)
        for (int b = 0; b < BATCH; ++b)
            g_seq[0][t][b][j] = xs[b * 128 + 2 * t] * A + C;
}

// SMEM-fed matvec: thread owns one gate row. acc[b] lanes = (even-k, odd-k) partials.
// ws: uint4[32][192] (+tid), v: float[4][256].
__device__ __forceinline__ void matvec_smem(const uint4* __restrict__ ws,
                                            const float* __restrict__ v,
                                            u64 acc[4], int tid) {
    #pragma unroll 4
    for (int kq = 0; kq < 32; ++kq) {
        uint4 w = ws[kq * 192 + tid];
        const float* vk = v + kq * 8;
        ulonglong2 p0 = *(const ulonglong2*)(vk);
        ulonglong2 p1 = *(const ulonglong2*)(vk + 4);
        ulonglong2 p2 = *(const ulonglong2*)(vk + 256);
        ulonglong2 p3 = *(const ulonglong2*)(vk + 260);
        ulonglong2 p4 = *(const ulonglong2*)(vk + 512);
        ulonglong2 p5 = *(const ulonglong2*)(vk + 516);
        ulonglong2 p6 = *(const ulonglong2*)(vk + 768);
        ulonglong2 p7 = *(const ulonglong2*)(vk + 772);
        u64 wv;
        wv = expand_bf2(w.x);
        fma2(acc[0], wv, p0.x); fma2(acc[1], wv, p2.x);
        fma2(acc[2], wv, p4.x); fma2(acc[3], wv, p6.x);
        wv = expand_bf2(w.y);
        fma2(acc[0], wv, p0.y); fma2(acc[1], wv, p2.y);
        fma2(acc[2], wv, p4.y); fma2(acc[3], wv, p6.y);
        wv = expand_bf2(w.z);
        fma2(acc[0], wv, p1.x); fma2(acc[1], wv, p3.x);
        fma2(acc[2], wv, p5.x); fma2(acc[3], wv, p7.x);
        wv = expand_bf2(w.w);
        fma2(acc[0], wv, p1.y); fma2(acc[1], wv, p3.y);
        fma2(acc[2], wv, p5.y); fma2(acc[3], wv, p7.y);
    }
}

// Quarter-layer wavefront: 2048 blocks = 512 layers x 4 quarters, 192 threads,
// 1 block/SM (211KB smem). Quarter q owns units [q*64, q*64+64), all 3 gates:
// thread tid -> gate gi=tid/64, unit u=tid%64, weight row = gi*256 + q*64 + u.
// Prologue packs this block's fp32 weight rows into SMEM as bf16 pairs; the
// 64-step main loop touches NO global weights.
__global__ void __launch_bounds__(192)
gru_wave_kernel(const float* __restrict__ eih, const float* __restrict__ ehh,
                const float* __restrict__ ebih, const float* __restrict__ ebhh,
                const float* __restrict__ dih, const float* __restrict__ dhh,
                const float* __restrict__ dbih, const float* __restrict__ dbhh) {
    extern __shared__ __align__(16) char smem[];
    uint4* wih_s = (uint4*)smem;                    // 32*192 uint4 = 96KB
    uint4* whh_s = wih_s + 32 * 192;                // 96KB
    float* xs  = (float*)(whh_s + 32 * 192);        // 4*256
    float* hs  = xs + 1024;                         // 4*256
    float* gxs = hs + 1024;                         // 4*192
    float* ghs = gxs + 4 * 192;                     // 4*192

    const int bid = blockIdx.x;
    const int tid = threadIdx.x;
    const int pairIdx = bid >> 2;                   // global layer 0..511
    const int q = bid & 3;
    const bool enc = pairIdx < NLAY;
    const int l = pairIdx & (NLAY - 1);
    const int u = tid & 63;
    const int gi = tid >> 6;                        // 0=r 1=z 2=n
    const int row = gi * 256 + q * 64 + u;

    // ---- prologue: pack this block's weight rows fp32 -> bf16 pairs in SMEM ----
    {
        const float* sih = (enc ? eih : dih) + ((size_t)l * GDIM + row) * HDIM;
        const float* shh = (enc ? ehh : dhh) + ((size_t)l * GDIM + row) * HDIM;
        #pragma unroll 4
        for (int kq = 0; kq < 32; ++kq) {
            float4 a = *(const float4*)(sih + kq * 8);
            float4 b = *(const float4*)(sih + kq * 8 + 4);
            wih_s[kq * 192 + tid] = make_uint4(packbf(a.x, a.y), packbf(a.z, a.w),
                                               packbf(b.x, b.y), packbf(b.z, b.w));
            float4 c = *(const float4*)(shh + kq * 8);
            float4 d = *(const float4*)(shh + kq * 8 + 4);
            whh_s[kq * 192 + tid] = make_uint4(packbf(c.x, c.y), packbf(c.z, c.w),
                                               packbf(d.x, d.y), packbf(d.z, d.w));
        }
    }
    const float bi = (enc ? ebih : dbih)[l * GDIM + row];
    const float bh = (enc ? ebhh : dbhh)[l * GDIM + row];

    const float* inp = enc ? &g_seq[l][0][0][0]
                           : (l == 0 ? &g_seq[NLAY][0][0][0] : &g_seq[l - 1][0][0][0]);
    float* outp = enc ? &g_seq[l + 1][0][0][0] : &g_seq[l][0][0][0];
    const bool relu_out = enc && (l == NLAY - 1);

    #pragma unroll
    for (int b = 0; b < 4; ++b) ghs[b * 192 + tid] = bh;   // h0=0 -> gh = bhh
    float ho[4] = {0.f, 0.f, 0.f, 0.f};                    // live in tid<64

    for (int t = 0; t < TSTEPS; ++t) {
        // --- A: wait for all 4 quarters of the previous layer, stage x_t ---
        if (pairIdx > 0 && tid < 4) {
            const int* pf = &g_flags[4 * (pairIdx - 1) + tid];
            int v;
            do {
                asm volatile("ld.acquire.gpu.global.u32 %0,[%1];"
                             : "=r"(v) : "l"(pf) : "memory");
                if (v > t) break;
                __nanosleep(20);
            } while (true);
        }
        __syncthreads();
        {
            const float* xt = inp + t * (BATCH * HDIM);
            #pragma unroll
            for (int i = tid; i < 1024; i += 192) xs[i] = xt[i];
        }
        __syncthreads();

        // --- B: ih matvec from SMEM ---
        {
            u64 acc[4] = {0ull, 0ull, 0ull, 0ull};
            matvec_smem(wih_s, xs, acc, tid);
            #pragma unroll
            for (int b = 0; b < 4; ++b) {
                float lo, hi; unpk2(acc[b], lo, hi);
                gxs[b * 192 + tid] = lo + hi + bi;
            }
        }
        __syncthreads();

        // --- C: gates for own 64 units, publish ---
        if (tid < 64) {
            #pragma unroll
            for (int b = 0; b < 4; ++b) {
                float r = sigm(gxs[b * 192 + u] + ghs[b * 192 + u]);
                float z = sigm(gxs[b * 192 + 64 + u] + ghs[b * 192 + 64 + u]);
                float n = tanhf(gxs[b * 192 + 128 + u] + r * ghs[b * 192 + 128 + u]);
                ho[b] = n + z * (ho[b] - n);               // (1-z)*n + z*h
                outp[t * (BATCH * HDIM) + b * HDIM + q * 64 + u] =
                    relu_out ? fmaxf(ho[b], 0.f) : ho[b];
            }
        }
        __syncthreads();
        if (tid == 0) {
            asm volatile("st.release.gpu.global.u32 [%0],%1;"
                         :: "l"(&g_flags[4 * pairIdx + q]), "r"(t + 1) : "memory");
        }

        // --- D: gh for t+1 (off the hop path): gather full h_t, hh matvec ---
        if (t < TSTEPS - 1) {
            if (tid < 4) {                                  // wait sibling quarters
                const int* sf = &g_flags[4 * pairIdx + tid];
                int v;
                do {
                    asm volatile("ld.acquire.gpu.global.u32 %0,[%1];"
                                 : "=r"(v) : "l"(sf) : "memory");
                    if (v > t) break;
                    __nanosleep(20);
                } while (true);
            }
            __syncthreads();
            {
                const float* ht = outp + t * (BATCH * HDIM);
                #pragma unroll
                for (int i = tid; i < 1024; i += 192) hs[i] = ht[i];
            }
            __syncthreads();
            u64 acc[4] = {0ull, 0ull, 0ull, 0ull};
            matvec_smem(whh_s, hs, acc, tid);
            #pragma unroll
            for (int b = 0; b < 4; ++b) {
                float lo, hi; unpk2(acc[b], lo, hi);
                ghs[b * 192 + tid] = lo + hi + bh;
            }
            // ghs read in next iteration's C, after A/B __syncthreads.
        }
    }
}

// Attention + FC + softmax tail. One block per timestep t.
__global__ void attn_fc_kernel(const float* __restrict__ fcl_w,
                               const float* __restrict__ fcl_b,
                               float* __restrict__ out) {
    const int t = blockIdx.x;
    const int tid = threadIdx.x;
    __shared__ float hid_s[BATCH][HDIM];
    __shared__ float sc[BATCH][TSTEPS];
    __shared__ float ctx[BATCH][HDIM];
    __shared__ float lg[BATCH][NCLS];

    #pragma unroll
    for (int b = 0; b < BATCH; ++b)
        hid_s[b][tid] = g_seq[NLAY - 1][t][b][tid];
    __syncthreads();

    int s = tid >> 2, qq = tid & 3;
    #pragma unroll
    for (int b = 0; b < BATCH; ++b) {
        const float* e = &g_seq[NLAY][s][b][0];
        float acc = 0.f;
        for (int d = qq * 64; d < qq * 64 + 64; ++d) acc += hid_s[b][d] * e[d];
        acc += __shfl_xor_sync(0xffffffff, acc, 1);
        acc += __shfl_xor_sync(0xffffffff, acc, 2);
        if (qq == 0) sc[b][s] = acc;
    }
    __syncthreads();

    if (tid < BATCH) {
        int b = tid;
        float m = -1e30f;
        for (int i = 0; i < TSTEPS; ++i) m = fmaxf(m, sc[b][i]);
        float sum = 0.f;
        for (int i = 0; i < TSTEPS; ++i) { float e = __expf(sc[b][i] - m); sc[b][i] = e; sum += e; }
        float inv = 1.f / sum;
        for (int i = 0; i < TSTEPS; ++i) sc[b][i] *= inv;
    }
    __syncthreads();

    #pragma unroll
    for (int b = 0; b < BATCH; ++b) {
        float acc = sc[b][0] * g_seq[NLAY][0][b][tid];
        for (int s2 = 0; s2 < TSTEPS - 1; ++s2)
            acc += sc[b][s2] * g_seq[NLAY][s2 + 1][b][tid];
        ctx[b][tid] = acc;
    }
    __syncthreads();

    if (tid < BATCH * NCLS) {
        int b = tid / NCLS, o = tid % NCLS;
        float acc = fcl_b[o];
        for (int f = 0; f < HDIM; ++f) acc += fcl_w[o * 2 * HDIM + f] * hid_s[b][f];
        for (int f = 0; f < HDIM; ++f) acc += fcl_w[o * 2 * HDIM + HDIM + f] * ctx[b][f];
        lg[b][o] = acc;
    }
    __syncthreads();

    if (tid < BATCH) {
        int b = tid;
        float m = -1e30f;
        for (int o = 0; o < NCLS; ++o) m = fmaxf(m, lg[b][o]);
        float ex[NCLS]; float sum = 0.f;
        for (int o = 0; o < NCLS; ++o) { ex[o] = __expf(lg[b][o] - m); sum += ex[o]; }
        float inv = 1.f / sum;
        for (int o = 0; o < NCLS; ++o)
            out[(t * BATCH + b) * NCLS + o] = ex[o] * inv;
    }
}

extern "C" void kernel_launch(void* const* d_in, const int* in_sizes, int n_in,
                              void* d_out, int out_size) {
    const float* X    = (const float*)d_in[0];
    const float* c1w  = (const float*)d_in[1];
    const float* c1b  = (const float*)d_in[2];
    const float* c2w  = (const float*)d_in[3];
    const float* c2b  = (const float*)d_in[4];
    const float* eih  = (const float*)d_in[5];
    const float* ehh  = (const float*)d_in[6];
    const float* ebih = (const float*)d_in[7];
    const float* ebhh = (const float*)d_in[8];
    const float* dih  = (const float*)d_in[9];
    const float* dhh  = (const float*)d_in[10];
    const float* dbih = (const float*)d_in[11];
    const float* dbhh = (const float*)d_in[12];
    const float* fclw = (const float*)d_in[13];
    const float* fclb = (const float*)d_in[14];
    float* out = (float*)d_out;

    const int SMEM_BYTES = 2 * 32 * 192 * 16 + (1024 + 1024 + 768 + 768) * 4; // 210944
    static int smem_set = 0;
    if (!smem_set) {
        cudaFuncSetAttribute(gru_wave_kernel,
                             cudaFuncAttributeMaxDynamicSharedMemorySize, SMEM_BYTES);
        smem_set = 1;
    }

    zero_flags_kernel<<<8, 256>>>();
    conv_front_kernel<<<1, 256>>>(X, c1w, c1b, c2w, c2b);
    gru_wave_kernel<<<8 * NLAY, 192, SMEM_BYTES>>>(eih, ehh, ebih, ebhh,
                                                   dih, dhh, dbih, dbhh);
    attn_fc_kernel<<<TSTEPS, 256>>>(fclw, fclb, out);
}

// round 14
// speedup vs baseline: 1.2093x; 1.2093x over previous
#include <cuda_runtime.h>
#include <cuda_bf16.h>

#define NLAY 256
#define TSTEPS 64
#define BATCH 4
#define HDIM 256
#define GDIM 768
#define NCLS 26

// Packed hh weights (global, L2-served): uint4 component c at
// [(l*32+kq)*768 + row] covers k = kq*8+2c (lo bf16) and k+1 (hi bf16).
// m: 0=enc_hh, 1=dec_hh.
#define MATSZ ((size_t)NLAY * 32 * 768 * 4)
__device__ unsigned g_wpackhh[2 * MATSZ];

// Sequence slots: enc layer l reads g_seq[l], writes g_seq[l+1] (slot 256 = relu'd emb).
// dec layer d reads g_seq[256] (d==0) else g_seq[d-1], writes g_seq[d].
__device__ float g_seq[NLAY + 1][TSTEPS][BATCH][HDIM];
// One flag per half-block: g_flags[2*pairIdx + half], pairIdx 0..511.
__device__ int g_flags[4 * NLAY];

typedef unsigned long long u64;

__device__ __forceinline__ void unpk2(u64 v, float& lo, float& hi) {
    asm("mov.b64 {%0,%1},%2;" : "=f"(lo), "=f"(hi) : "l"(v));
}
__device__ __forceinline__ u64 expand_bf2(unsigned u) {
    float lo = __uint_as_float(u << 16);
    float hi = __uint_as_float(u & 0xffff0000u);
    u64 r; asm("mov.b64 %0,{%1,%2};" : "=l"(r) : "f"(lo), "f"(hi)); return r;
}
__device__ __forceinline__ void fma2(u64& acc, u64 a, u64 b) {
    asm("fma.rn.f32x2 %0,%1,%2,%0;" : "+l"(acc) : "l"(a), "l"(b));
}
__device__ __forceinline__ float sigm(float x) { return 1.f / (1.f + __expf(-x)); }
__device__ __forceinline__ unsigned packbf(float f0, float f1) {
    return (unsigned)__bfloat16_as_ushort(__float2bfloat16(f0)) |
           ((unsigned)__bfloat16_as_ushort(__float2bfloat16(f1)) << 16);
}
__device__ __forceinline__ uint4 ldcg4(const uint4* p) {
    uint4 r;
    asm("ld.global.cg.v4.u32 {%0,%1,%2,%3},[%4];"
        : "=r"(r.x), "=r"(r.y), "=r"(r.z), "=r"(r.w) : "l"(p));
    return r;
}

__global__ void zero_flags_kernel() { g_flags[threadIdx.x] = 0; }

// Pointwise convs collapse: seq[0][t][b][h] = X[b,0,2t]*A[h] + C[h]
__global__ void conv_front_kernel(const float* __restrict__ X,
                                  const float* __restrict__ c1w,
                                  const float* __restrict__ c1b,
                                  const float* __restrict__ c2w,
                                  const float* __restrict__ c2b) {
    __shared__ float xs[512];
    int j = threadIdx.x;
    xs[j] = X[j];
    xs[256 + j] = X[256 + j];
    __syncthreads();
    float A = 0.f, C = 0.f;
    for (int c = 0; c < 128; ++c) {
        float w2 = c2w[j * 128 + c];
        A += w2 * c1w[c];
        C += w2 * c1b[c];
    }
    C += c2b[j];
    for (int t = 0; t < TSTEPS; ++t)
        for (int b = 0; b < BATCH; ++b)
            g_seq[0][t][b][j] = xs[b * 128 + 2 * t] * A + C;
}

// Repack hh fp32 [l][g][k] -> bf16-pair uint4 layout (global). grid = 2*256*48.
__global__ void pack_hh_kernel(const float* __restrict__ ehh,
                               const float* __restrict__ dhh) {
    __shared__ float tile[64][65];
    int bid = blockIdx.x;
    int m = bid / 12288;
    int r = bid % 12288;
    int l = r / 48;
    int r2 = r % 48;
    int gt = r2 / 4;
    int kt = r2 % 4;
    const float* src = (m == 0) ? ehh : dhh;
    int tid = threadIdx.x;
    #pragma unroll
    for (int i = 0; i < 16; ++i) {
        int idx = tid + i * 256;
        int gg = idx >> 6, kk = idx & 63;
        tile[gg][kk] = src[((size_t)l * GDIM + gt * 64 + gg) * HDIM + kt * 64 + kk];
    }
    __syncthreads();
    #pragma unroll
    for (int i = 0; i < 8; ++i) {
        int o = tid + i * 256;
        int gg = o & 63, kp = o >> 6;
        unsigned u = packbf(tile[gg][2 * kp], tile[gg][2 * kp + 1]);
        size_t dst = (((size_t)l * 32 + kt * 8 + (kp >> 2)) * 768 + gt * 64 + gg) * 4 + (kp & 3);
        g_wpackhh[(size_t)m * MATSZ + dst] = u;
    }
}

// ih matvec from SMEM weights: ws[kq*384 + tid]; v = float[4][256].
// acc[b] lanes = (even-k, odd-k) partial sums for batch b.
__device__ __forceinline__ void matvec_smem(const uint4* __restrict__ ws,
                                            const float* __restrict__ v,
                                            u64 acc[4], int tid) {
    #pragma unroll 4
    for (int kq = 0; kq < 32; ++kq) {
        uint4 w = ws[kq * 384 + tid];
        const float* vk = v + kq * 8;
        ulonglong2 p0 = *(const ulonglong2*)(vk);
        ulonglong2 p1 = *(const ulonglong2*)(vk + 4);
        ulonglong2 p2 = *(const ulonglong2*)(vk + 256);
        ulonglong2 p3 = *(const ulonglong2*)(vk + 260);
        ulonglong2 p4 = *(const ulonglong2*)(vk + 512);
        ulonglong2 p5 = *(const ulonglong2*)(vk + 516);
        ulonglong2 p6 = *(const ulonglong2*)(vk + 768);
        ulonglong2 p7 = *(const ulonglong2*)(vk + 772);
        u64 wv;
        wv = expand_bf2(w.x);
        fma2(acc[0], wv, p0.x); fma2(acc[1], wv, p2.x);
        fma2(acc[2], wv, p4.x); fma2(acc[3], wv, p6.x);
        wv = expand_bf2(w.y);
        fma2(acc[0], wv, p0.y); fma2(acc[1], wv, p2.y);
        fma2(acc[2], wv, p4.y); fma2(acc[3], wv, p6.y);
        wv = expand_bf2(w.z);
        fma2(acc[0], wv, p1.x); fma2(acc[1], wv, p3.x);
        fma2(acc[2], wv, p5.x); fma2(acc[3], wv, p7.x);
        wv = expand_bf2(w.w);
        fma2(acc[0], wv, p1.y); fma2(acc[1], wv, p3.y);
        fma2(acc[2], wv, p5.y); fma2(acc[3], wv, p7.y);
    }
}

// hh matvec from global (L2 via .cg), stride 768 uint4 per kq.
__device__ __forceinline__ void matvec_glob(const uint4* __restrict__ wp,
                                            const float* __restrict__ v,
                                            u64 acc[4]) {
    #pragma unroll 4
    for (int kq = 0; kq < 32; ++kq) {
        uint4 w = ldcg4(wp); wp += 768;
        const float* vk = v + kq * 8;
        ulonglong2 p0 = *(const ulonglong2*)(vk);
        ulonglong2 p1 = *(const ulonglong2*)(vk + 4);
        ulonglong2 p2 = *(const ulonglong2*)(vk + 256);
        ulonglong2 p3 = *(const ulonglong2*)(vk + 260);
        ulonglong2 p4 = *(const ulonglong2*)(vk + 512);
        ulonglong2 p5 = *(const ulonglong2*)(vk + 516);
        ulonglong2 p6 = *(const ulonglong2*)(vk + 768);
        ulonglong2 p7 = *(const ulonglong2*)(vk + 772);
        u64 wv;
        wv = expand_bf2(w.x);
        fma2(acc[0], wv, p0.x); fma2(acc[1], wv, p2.x);
        fma2(acc[2], wv, p4.x); fma2(acc[3], wv, p6.x);
        wv = expand_bf2(w.y);
        fma2(acc[0], wv, p0.y); fma2(acc[1], wv, p2.y);
        fma2(acc[2], wv, p4.y); fma2(acc[3], wv, p6.y);
        wv = expand_bf2(w.z);
        fma2(acc[0], wv, p1.x); fma2(acc[1], wv, p3.x);
        fma2(acc[2], wv, p5.x); fma2(acc[3], wv, p7.x);
        wv = expand_bf2(w.w);
        fma2(acc[0], wv, p1.y); fma2(acc[1], wv, p3.y);
        fma2(acc[2], wv, p5.y); fma2(acc[3], wv, p7.y);
    }
}

// Half-layer wavefront: 1024 blocks = 512 layers x 2 halves, 384 threads,
// 1 block/SM (217KB smem: ih weights live in SMEM). Half owns units
// [half*128, half*128+128): tid -> gate gi=tid/128, unit u=tid%128,
// weight row = gi*256 + half*128 + u.
// Hop path: wait prev layer -> stage x -> ih matvec (SMEM) -> gates -> publish.
// hh matvec (L2 .cg) runs after publish, off the hop path.
__global__ void __launch_bounds__(384)
gru_wave_kernel(const float* __restrict__ eih, const float* __restrict__ dih,
                const float* __restrict__ ebih, const float* __restrict__ ebhh,
                const float* __restrict__ dbih, const float* __restrict__ dbhh) {
    extern __shared__ __align__(16) char smem[];
    uint4* wih_s = (uint4*)smem;                 // 32*384 uint4 = 196608 B
    float* xs  = (float*)(wih_s + 32 * 384);     // 4*256
    float* hs  = xs + 1024;                      // 4*256
    float* gxs = hs + 1024;                      // 4*384
    float* ghs = gxs + 4 * 384;                  // 4*384

    const int bid = blockIdx.x;
    const int tid = threadIdx.x;
    const int pairIdx = bid >> 1;                // global layer 0..511
    const int half = bid & 1;
    const bool enc = pairIdx < NLAY;
    const int l = pairIdx & (NLAY - 1);
    const int u = tid & 127;
    const int row = (tid >> 7) * 256 + half * 128 + u;

    // ---- prologue: pack ih fp32 -> bf16 pairs in SMEM (coalesced reads) ----
    {
        const float* src = (enc ? eih : dih);
        unsigned* w32 = (unsigned*)wih_s;
        #pragma unroll
        for (int g = 0; g < 3; ++g) {
            const float4* base = (const float4*)
                (src + ((size_t)l * GDIM + g * 256 + half * 128) * HDIM);
            for (int idx = tid; idx < 128 * 64; idx += 384) {   // 8192 float4s
                float4 f = base[idx];
                int k  = (idx << 2) & 255;
                int lr = g * 128 + (idx >> 6);
                int kq = k >> 3;
                int c  = (k & 7) >> 1;                          // 0 or 2
                int s  = (kq * 384 + lr) * 4 + c;
                w32[s]     = packbf(f.x, f.y);
                w32[s + 1] = packbf(f.z, f.w);
            }
        }
    }
    const uint4* whh = (const uint4*)(g_wpackhh + (size_t)(enc ? 0 : 1) * MATSZ)
                       + ((size_t)l * 32 * 768 + row);

    const float bi = (enc ? ebih : dbih)[l * GDIM + row];
    const float bh = (enc ? ebhh : dbhh)[l * GDIM + row];

    const float* inp = enc ? &g_seq[l][0][0][0]
                           : (l == 0 ? &g_seq[NLAY][0][0][0] : &g_seq[l - 1][0][0][0]);
    float* outp = enc ? &g_seq[l + 1][0][0][0] : &g_seq[l][0][0][0];
    const bool relu_out = enc && (l == NLAY - 1);
    const int* pf0 = &g_flags[2 * (pairIdx - 1)];      // valid only if pairIdx>0
    const int* pf1 = &g_flags[2 * (pairIdx - 1) + 1];
    const int* peerflag = &g_flags[bid ^ 1];
    int* myflag = &g_flags[bid];

    #pragma unroll
    for (int b = 0; b < 4; ++b) ghs[b * 384 + tid] = bh;   // h0=0 -> gh = bhh
    float ho[4] = {0.f, 0.f, 0.f, 0.f};                    // live in tid<128
    __syncthreads();                                       // prologue done

    for (int t = 0; t < TSTEPS; ++t) {
        // --- A: wait for both halves of the previous layer, stage x_t ---
        if (tid == 0 && pairIdx > 0) {
            int v;
            do {
                asm volatile("ld.acquire.gpu.global.u32 %0,[%1];"
                             : "=r"(v) : "l"(pf0) : "memory");
                if (v > t) break;
                __nanosleep(20);
            } while (true);
            do {
                asm volatile("ld.acquire.gpu.global.u32 %0,[%1];"
                             : "=r"(v) : "l"(pf1) : "memory");
                if (v > t) break;
                __nanosleep(20);
            } while (true);
        }
        __syncthreads();
        {
            const float* xt = inp + t * (BATCH * HDIM);
            #pragma unroll
            for (int i = tid; i < 1024; i += 384) xs[i] = xt[i];
        }
        __syncthreads();

        // --- B: ih matvec from SMEM (critical path) ---
        {
            u64 acc[4] = {0ull, 0ull, 0ull, 0ull};
            matvec_smem(wih_s, xs, acc, tid);
            #pragma unroll
            for (int b = 0; b < 4; ++b) {
                float lo, hi; unpk2(acc[b], lo, hi);
                gxs[b * 384 + tid] = lo + hi + bi;
            }
        }
        __syncthreads();

        // --- C: gates for own 128 units, publish own h half ---
        if (tid < 128) {
            #pragma unroll
            for (int b = 0; b < 4; ++b) {
                float r = sigm(gxs[b * 384 + u] + ghs[b * 384 + u]);
                float z = sigm(gxs[b * 384 + 128 + u] + ghs[b * 384 + 128 + u]);
                float n = tanhf(gxs[b * 384 + 256 + u] + r * ghs[b * 384 + 256 + u]);
                ho[b] = n + z * (ho[b] - n);               // (1-z)*n + z*h
                hs[b * 256 + half * 128 + u] = ho[b];
                outp[t * (BATCH * HDIM) + b * HDIM + half * 128 + u] =
                    relu_out ? fmaxf(ho[b], 0.f) : ho[b];
            }
        }
        __syncthreads();
        if (tid == 0) {
            asm volatile("st.release.gpu.global.u32 [%0],%1;"
                         :: "l"(myflag), "r"(t + 1) : "memory");
        }

        // --- D: gh for t+1 (off hop path): fetch peer h half, hh matvec (L2) ---
        if (t < TSTEPS - 1) {
            if (tid == 0) {
                int v;
                do {
                    asm volatile("ld.acquire.gpu.global.u32 %0,[%1];"
                                 : "=r"(v) : "l"(peerflag) : "memory");
                    if (v > t) break;
                    __nanosleep(20);
                } while (true);
            }
            __syncthreads();
            {
                int ph = (half ^ 1) * 128;
                for (int i = tid; i < 512; i += 384) {
                    int b = i >> 7, uu = i & 127;
                    hs[b * 256 + ph + uu] = outp[t * (BATCH * HDIM) + b * HDIM + ph + uu];
                }
            }
            __syncthreads();
            u64 acc[4] = {0ull, 0ull, 0ull, 0ull};
            matvec_glob(whh, hs, acc);
            #pragma unroll
            for (int b = 0; b < 4; ++b) {
                float lo, hi; unpk2(acc[b], lo, hi);
                ghs[b * 384 + tid] = lo + hi + bh;
            }
            // ghs read next iteration in C, after A/B __syncthreads.
        }
    }
}

// Attention + FC + softmax tail. One block per timestep t.
__global__ void attn_fc_kernel(const float* __restrict__ fcl_w,
                               const float* __restrict__ fcl_b,
                               float* __restrict__ out) {
    const int t = blockIdx.x;
    const int tid = threadIdx.x;
    __shared__ float hid_s[BATCH][HDIM];
    __shared__ float sc[BATCH][TSTEPS];
    __shared__ float ctx[BATCH][HDIM];
    __shared__ float lg[BATCH][NCLS];

    #pragma unroll
    for (int b = 0; b < BATCH; ++b)
        hid_s[b][tid] = g_seq[NLAY - 1][t][b][tid];
    __syncthreads();

    int s = tid >> 2, qq = tid & 3;
    #pragma unroll
    for (int b = 0; b < BATCH; ++b) {
        const float* e = &g_seq[NLAY][s][b][0];
        float acc = 0.f;
        for (int d = qq * 64; d < qq * 64 + 64; ++d) acc += hid_s[b][d] * e[d];
        acc += __shfl_xor_sync(0xffffffff, acc, 1);
        acc += __shfl_xor_sync(0xffffffff, acc, 2);
        if (qq == 0) sc[b][s] = acc;
    }
    __syncthreads();

    if (tid < BATCH) {
        int b = tid;
        float m = -1e30f;
        for (int i = 0; i < TSTEPS; ++i) m = fmaxf(m, sc[b][i]);
        float sum = 0.f;
        for (int i = 0; i < TSTEPS; ++i) { float e = __expf(sc[b][i] - m); sc[b][i] = e; sum += e; }
        float inv = 1.f / sum;
        for (int i = 0; i < TSTEPS; ++i) sc[b][i] *= inv;
    }
    __syncthreads();

    #pragma unroll
    for (int b = 0; b < BATCH; ++b) {
        float acc = sc[b][0] * g_seq[NLAY][0][b][tid];
        for (int s2 = 0; s2 < TSTEPS - 1; ++s2)
            acc += sc[b][s2] * g_seq[NLAY][s2 + 1][b][tid];
        ctx[b][tid] = acc;
    }
    __syncthreads();

    if (tid < BATCH * NCLS) {
        int b = tid / NCLS, o = tid % NCLS;
        float acc = fcl_b[o];
        for (int f = 0; f < HDIM; ++f) acc += fcl_w[o * 2 * HDIM + f] * hid_s[b][f];
        for (int f = 0; f < HDIM; ++f) acc += fcl_w[o * 2 * HDIM + HDIM + f] * ctx[b][f];
        lg[b][o] = acc;
    }
    __syncthreads();

    if (tid < BATCH) {
        int b = tid;
        float m = -1e30f;
        for (int o = 0; o < NCLS; ++o) m = fmaxf(m, lg[b][o]);
        float ex[NCLS]; float sum = 0.f;
        for (int o = 0; o < NCLS; ++o) { ex[o] = __expf(lg[b][o] - m); sum += ex[o]; }
        float inv = 1.f / sum;
        for (int o = 0; o < NCLS; ++o)
            out[(t * BATCH + b) * NCLS + o] = ex[o] * inv;
    }
}

extern "C" void kernel_launch(void* const* d_in, const int* in_sizes, int n_in,
                              void* d_out, int out_size) {
    const float* X    = (const float*)d_in[0];
    const float* c1w  = (const float*)d_in[1];
    const float* c1b  = (const float*)d_in[2];
    const float* c2w  = (const float*)d_in[3];
    const float* c2b  = (const float*)d_in[4];
    const float* eih  = (const float*)d_in[5];
    const float* ehh  = (const float*)d_in[6];
    const float* ebih = (const float*)d_in[7];
    const float* ebhh = (const float*)d_in[8];
    const float* dih  = (const float*)d_in[9];
    const float* dhh  = (const float*)d_in[10];
    const float* dbih = (const float*)d_in[11];
    const float* dbhh = (const float*)d_in[12];
    const float* fclw = (const float*)d_in[13];
    const float* fclb = (const float*)d_in[14];
    float* out = (float*)d_out;

    // ih smem weights 196608 + xs 4096 + hs 4096 + gxs 6144 + ghs 6144
    const int SMEM_BYTES = 196608 + 4096 + 4096 + 6144 + 6144;   // 217088
    static int smem_set = 0;
    if (!smem_set) {
        cudaFuncSetAttribute(gru_wave_kernel,
                             cudaFuncAttributeMaxDynamicSharedMemorySize, SMEM_BYTES);
        smem_set = 1;
    }

    zero_flags_kernel<<<1, 4 * NLAY>>>();
    conv_front_kernel<<<1, 256>>>(X, c1w, c1b, c2w, c2b);
    pack_hh_kernel<<<2 * 256 * 48, 256>>>(ehh, dhh);
    gru_wave_kernel<<<4 * NLAY, 384, SMEM_BYTES>>>(eih, dih, ebih, ebhh, dbih, dbhh);
    attn_fc_kernel<<<TSTEPS, 256>>>(fclw, fclb, out);
}

// round 16
// speedup vs baseline: 1.2367x; 1.0227x over previous
#include <cuda_runtime.h>
#include <cuda_bf16.h>

#define NLAY 256
#define TSTEPS 64
#define BATCH 4
#define HDIM 256
#define GDIM 768
#define NCLS 26

// Packed bf16-pair weights, uint4 per (kq, gate-row):
//   uint4 at [(l*32+kq)*768 + row]; u32 component c covers k = kq*8+2c (lo), +1 (hi).
// Matrices: 0=enc_ih 1=enc_hh 2=dec_ih 3=dec_hh, each MATSZ u32s.
#define MATSZ ((size_t)NLAY * 32 * 768 * 4)
__device__ unsigned g_wpack4[4 * MATSZ];

// Sequence slots: enc layer l reads g_seq[l], writes g_seq[l+1] (slot 256 = relu'd emb).
// dec layer d reads g_seq[256] (d==0) else g_seq[d-1], writes g_seq[d].
__device__ float g_seq[NLAY + 1][TSTEPS][BATCH][HDIM];
// One flag per quarter-block: g_flags[4*pairIdx + q], pairIdx 0..511.
__device__ int g_flags[8 * NLAY];

typedef unsigned long long u64;

__device__ __forceinline__ void unpk2(u64 v, float& lo, float& hi) {
    asm("mov.b64 {%0,%1},%2;" : "=f"(lo), "=f"(hi) : "l"(v));
}
__device__ __forceinline__ u64 expand_bf2(unsigned u) {
    float lo = __uint_as_float(u << 16);
    float hi = __uint_as_float(u & 0xffff0000u);
    u64 r; asm("mov.b64 %0,{%1,%2};" : "=l"(r) : "f"(lo), "f"(hi)); return r;
}
__device__ __forceinline__ void fma2(u64& acc, u64 a, u64 b) {
    asm("fma.rn.f32x2 %0,%1,%2,%0;" : "+l"(acc) : "l"(a), "l"(b));
}
__device__ __forceinline__ float sigm(float x) { return 1.f / (1.f + __expf(-x)); }
__device__ __forceinline__ unsigned packbf(float f0, float f1) {
    return (unsigned)__bfloat16_as_ushort(__float2bfloat16(f0)) |
           ((unsigned)__bfloat16_as_ushort(__float2bfloat16(f1)) << 16);
}
__device__ __forceinline__ uint4 ldcg4(const uint4* p) {
    uint4 r;
    asm("ld.global.cg.v4.u32 {%0,%1,%2,%3},[%4];"
        : "=r"(r.x), "=r"(r.y), "=r"(r.z), "=r"(r.w) : "l"(p));
    return r;
}

__global__ void zero_flags_kernel() {
    int i = blockIdx.x * blockDim.x + threadIdx.x;
    if (i < 8 * NLAY) g_flags[i] = 0;
}

// Pointwise convs collapse: seq[0][t][b][h] = X[b,0,2t]*A[h] + C[h]
__global__ void conv_front_kernel(const float* __restrict__ X,
                                  const float* __restrict__ c1w,
                                  const float* __restrict__ c1b,
                                  const float* __restrict__ c2w,
                                  const float* __restrict__ c2b) {
    __shared__ float xs[512];
    int j = threadIdx.x;
    xs[j] = X[j];
    xs[256 + j] = X[256 + j];
    __syncthreads();
    float A = 0.f, C = 0.f;
    for (int c = 0; c < 128; ++c) {
        float w2 = c2w[j * 128 + c];
        A += w2 * c1w[c];
        C += w2 * c1b[c];
    }
    C += c2b[j];
    for (int t = 0; t < TSTEPS; ++t)
        for (int b = 0; b < BATCH; ++b)
            g_seq[0][t][b][j] = xs[b * 128 + 2 * t] * A + C;
}

// Repack fp32 [l][g][k] -> bf16-pair uint4 layout. grid = 4 * 256 * 48 blocks.
__global__ void pack_weights_kernel(const float* __restrict__ eih,
                                    const float* __restrict__ ehh,
                                    const float* __restrict__ dih,
                                    const float* __restrict__ dhh) {
    __shared__ float tile[64][65];
    int bid = blockIdx.x;
    int m = bid / 12288;
    int r = bid % 12288;
    int l = r / 48;
    int r2 = r % 48;
    int gt = r2 / 4;
    int kt = r2 % 4;
    const float* src = (m == 0) ? eih : (m == 1) ? ehh : (m == 2) ? dih : dhh;
    int tid = threadIdx.x;
    #pragma unroll
    for (int i = 0; i < 16; ++i) {
        int idx = tid + i * 256;
        int gg = idx >> 6, kk = idx & 63;
        tile[gg][kk] = src[((size_t)l * GDIM + gt * 64 + gg) * HDIM + kt * 64 + kk];
    }
    __syncthreads();
    #pragma unroll
    for (int i = 0; i < 8; ++i) {
        int o = tid + i * 256;
        int gg = o & 63, kp = o >> 6;
        unsigned u = packbf(tile[gg][2 * kp], tile[gg][2 * kp + 1]);
        size_t dst = (((size_t)l * 32 + kt * 8 + (kp >> 2)) * 768 + gt * 64 + gg) * 4 + (kp & 3);
        g_wpack4[(size_t)m * MATSZ + dst] = u;
    }
}

// Matvec for one gate row over 4 batches: weights from L2 (.cg), vector from smem.
// acc[b] lanes = (even-k, odd-k) partial sums for batch b.
__device__ __forceinline__ void matvec_glob(const uint4* __restrict__ wp,
                                            const float* __restrict__ v,
                                            u64 acc[4]) {
    #pragma unroll 4
    for (int kq = 0; kq < 32; ++kq) {
        uint4 w = ldcg4(wp); wp += 768;
        const float* vk = v + kq * 8;
        ulonglong2 p0 = *(const ulonglong2*)(vk);
        ulonglong2 p1 = *(const ulonglong2*)(vk + 4);
        ulonglong2 p2 = *(const ulonglong2*)(vk + 256);
        ulonglong2 p3 = *(const ulonglong2*)(vk + 260);
        ulonglong2 p4 = *(const ulonglong2*)(vk + 512);
        ulonglong2 p5 = *(const ulonglong2*)(vk + 516);
        ulonglong2 p6 = *(const ulonglong2*)(vk + 768);
        ulonglong2 p7 = *(const ulonglong2*)(vk + 772);
        u64 wv;
        wv = expand_bf2(w.x);
        fma2(acc[0], wv, p0.x); fma2(acc[1], wv, p2.x);
        fma2(acc[2], wv, p4.x); fma2(acc[3], wv, p6.x);
        wv = expand_bf2(w.y);
        fma2(acc[0], wv, p0.y); fma2(acc[1], wv, p2.y);
        fma2(acc[2], wv, p4.y); fma2(acc[3], wv, p6.y);
        wv = expand_bf2(w.z);
        fma2(acc[0], wv, p1.x); fma2(acc[1], wv, p3.x);
        fma2(acc[2], wv, p5.x); fma2(acc[3], wv, p7.x);
        wv = expand_bf2(w.w);
        fma2(acc[0], wv, p1.y); fma2(acc[1], wv, p3.y);
        fma2(acc[2], wv, p5.y); fma2(acc[3], wv, p7.y);
    }
}

// Quarter-layer wavefront: 2048 blocks = 512 layers x 4 quarters, 192 threads,
// 6 blocks/SM (high occupancy for latency hiding). Quarter q owns units
// [q*64, q*64+64), all 3 gates: tid -> gate gi=tid/64 (0=r,1=z,2=n),
// unit u=tid%64, weight row = gi*256 + q*64 + u.
// Hop path: wait prev layer (4 flags) -> stage x -> ih matvec -> gates -> publish.
// hh matvec for t+1 runs after publish (off the hop path), gathering full h_t.
__global__ void __launch_bounds__(192, 6)
gru_wave_kernel(const float* __restrict__ ebih, const float* __restrict__ ebhh,
                const float* __restrict__ dbih, const float* __restrict__ dbhh) {
    __shared__ __align__(16) float xs[1024];        // x_t  [b][k]
    __shared__ __align__(16) float hs[1024];        // h_t  [b][k]
    __shared__ float gxs[4 * 192];
    __shared__ float ghs[4 * 192];

    const int bid = blockIdx.x;
    const int tid = threadIdx.x;
    const int pairIdx = bid >> 2;                   // global layer 0..511
    const int q = bid & 3;
    const bool enc = pairIdx < NLAY;
    const int l = pairIdx & (NLAY - 1);
    const int u = tid & 63;
    const int gi = tid >> 6;                        // 0=r 1=z 2=n
    const int row = gi * 256 + q * 64 + u;

    const uint4* wih = (const uint4*)(g_wpack4 + (size_t)(enc ? 0 : 2) * MATSZ)
                       + ((size_t)l * 32 * 768 + row);
    const uint4* whh = (const uint4*)(g_wpack4 + (size_t)(enc ? 1 : 3) * MATSZ)
                       + ((size_t)l * 32 * 768 + row);

    const float bi = (enc ? ebih : dbih)[l * GDIM + row];
    const float bh = (enc ? ebhh : dbhh)[l * GDIM + row];

    const float* inp = enc ? &g_seq[l][0][0][0]
                           : (l == 0 ? &g_seq[NLAY][0][0][0] : &g_seq[l - 1][0][0][0]);
    float* outp = enc ? &g_seq[l + 1][0][0][0] : &g_seq[l][0][0][0];
    const bool relu_out = enc && (l == NLAY - 1);

    #pragma unroll
    for (int b = 0; b < 4; ++b) ghs[b * 192 + tid] = bh;   // h0=0 -> gh = bhh
    float ho[4] = {0.f, 0.f, 0.f, 0.f};                    // live in tid<64

    for (int t = 0; t < TSTEPS; ++t) {
        // --- A: wait for all 4 quarters of the previous layer, stage x_t ---
        if (pairIdx > 0 && tid < 4) {
            const int* pf = &g_flags[4 * (pairIdx - 1) + tid];
            int v;
            do {
                asm volatile("ld.acquire.gpu.global.u32 %0,[%1];"
                             : "=r"(v) : "l"(pf) : "memory");
                if (v > t) break;
                __nanosleep(20);
            } while (true);
        }
        __syncthreads();
        {
            const float* xt = inp + t * (BATCH * HDIM);
            #pragma unroll
            for (int i = 0; i < 6; ++i) {           // 6*192 >= 1024 (FIX: was 5)
                int idx = tid + i * 192;
                if (idx < 1024) xs[idx] = xt[idx];
            }
        }
        __syncthreads();

        // --- B: ih matvec (critical path) ---
        {
            u64 acc[4] = {0ull, 0ull, 0ull, 0ull};
            matvec_glob(wih, xs, acc);
            #pragma unroll
            for (int b = 0; b < 4; ++b) {
                float lo, hi; unpk2(acc[b], lo, hi);
                gxs[b * 192 + tid] = lo + hi + bi;
            }
        }
        __syncthreads();

        // --- C: gates for own 64 units, publish ---
        if (tid < 64) {
            #pragma unroll
            for (int b = 0; b < 4; ++b) {
                float r = sigm(gxs[b * 192 + u] + ghs[b * 192 + u]);
                float z = sigm(gxs[b * 192 + 64 + u] + ghs[b * 192 + 64 + u]);
                float n = tanhf(gxs[b * 192 + 128 + u] + r * ghs[b * 192 + 128 + u]);
                ho[b] = n + z * (ho[b] - n);               // (1-z)*n + z*h
                outp[t * (BATCH * HDIM) + b * HDIM + q * 64 + u] =
                    relu_out ? fmaxf(ho[b], 0.f) : ho[b];
            }
        }
        __syncthreads();
        if (tid == 0) {
            asm volatile("st.release.gpu.global.u32 [%0],%1;"
                         :: "l"(&g_flags[4 * pairIdx + q]), "r"(t + 1) : "memory");
        }

        // --- D: gh for t+1 (off the hop path): gather full h_t, hh matvec ---
        if (t < TSTEPS - 1) {
            if (tid < 4) {                                  // wait sibling quarters
                const int* sf = &g_flags[4 * pairIdx + tid];
                int v;
                do {
                    asm volatile("ld.acquire.gpu.global.u32 %0,[%1];"
                                 : "=r"(v) : "l"(sf) : "memory");
                    if (v > t) break;
                    __nanosleep(20);
                } while (true);
            }
            __syncthreads();
            {
                const float* ht = outp + t * (BATCH * HDIM);
                #pragma unroll
                for (int i = 0; i < 6; ++i) {       // 6*192 >= 1024 (FIX: was 5)
                    int idx = tid + i * 192;
                    if (idx < 1024) hs[idx] = ht[idx];
                }
            }
            __syncthreads();
            u64 acc[4] = {0ull, 0ull, 0ull, 0ull};
            matvec_glob(whh, hs, acc);
            #pragma unroll
            for (int b = 0; b < 4; ++b) {
                float lo, hi; unpk2(acc[b], lo, hi);
                ghs[b * 192 + tid] = lo + hi + bh;
            }
            // ghs read next iteration in C, after A/B __syncthreads.
        }
    }
}

// Attention + FC + softmax tail. One block per timestep t.
__global__ void attn_fc_kernel(const float* __restrict__ fcl_w,
                               const float* __restrict__ fcl_b,
                               float* __restrict__ out) {
    const int t = blockIdx.x;
    const int tid = threadIdx.x;
    __shared__ float hid_s[BATCH][HDIM];
    __shared__ float sc[BATCH][TSTEPS];
    __shared__ float ctx[BATCH][HDIM];
    __shared__ float lg[BATCH][NCLS];

    #pragma unroll
    for (int b = 0; b < BATCH; ++b)
        hid_s[b][tid] = g_seq[NLAY - 1][t][b][tid];
    __syncthreads();

    int s = tid >> 2, qq = tid & 3;
    #pragma unroll
    for (int b = 0; b < BATCH; ++b) {
        const float* e = &g_seq[NLAY][s][b][0];
        float acc = 0.f;
        for (int d = qq * 64; d < qq * 64 + 64; ++d) acc += hid_s[b][d] * e[d];
        acc += __shfl_xor_sync(0xffffffff, acc, 1);
        acc += __shfl_xor_sync(0xffffffff, acc, 2);
        if (qq == 0) sc[b][s] = acc;
    }
    __syncthreads();

    if (tid < BATCH) {
        int b = tid;
        float m = -1e30f;
        for (int i = 0; i < TSTEPS; ++i) m = fmaxf(m, sc[b][i]);
        float sum = 0.f;
        for (int i = 0; i < TSTEPS; ++i) { float e = __expf(sc[b][i] - m); sc[b][i] = e; sum += e; }
        float inv = 1.f / sum;
        for (int i = 0; i < TSTEPS; ++i) sc[b][i] *= inv;
    }
    __syncthreads();

    #pragma unroll
    for (int b = 0; b < BATCH; ++b) {
        float acc = sc[b][0] * g_seq[NLAY][0][b][tid];
        for (int s2 = 0; s2 < TSTEPS - 1; ++s2)
            acc += sc[b][s2] * g_seq[NLAY][s2 + 1][b][tid];
        ctx[b][tid] = acc;
    }
    __syncthreads();

    if (tid < BATCH * NCLS) {
        int b = tid / NCLS, o = tid % NCLS;
        float acc = fcl_b[o];
        for (int f = 0; f < HDIM; ++f) acc += fcl_w[o * 2 * HDIM + f] * hid_s[b][f];
        for (int f = 0; f < HDIM; ++f) acc += fcl_w[o * 2 * HDIM + HDIM + f] * ctx[b][f];
        lg[b][o] = acc;
    }
    __syncthreads();

    if (tid < BATCH) {
        int b = tid;
        float m = -1e30f;
        for (int o = 0; o < NCLS; ++o) m = fmaxf(m, lg[b][o]);
        float ex[NCLS]; float sum = 0.f;
        for (int o = 0; o < NCLS; ++o) { ex[o] = __expf(lg[b][o] - m); sum += ex[o]; }
        float inv = 1.f / sum;
        for (int o = 0; o < NCLS; ++o)
            out[(t * BATCH + b) * NCLS + o] = ex[o] * inv;
    }
}

extern "C" void kernel_launch(void* const* d_in, const int* in_sizes, int n_in,
                              void* d_out, int out_size) {
    const float* X    = (const float*)d_in[0];
    const float* c1w  = (const float*)d_in[1];
    const float* c1b  = (const float*)d_in[2];
    const float* c2w  = (const float*)d_in[3];
    const float* c2b  = (const float*)d_in[4];
    const float* eih  = (const float*)d_in[5];
    const float* ehh  = (const float*)d_in[6];
    const float* ebih = (const float*)d_in[7];
    const float* ebhh = (const float*)d_in[8];
    const float* dih  = (const float*)d_in[9];
    const float* dhh  = (const float*)d_in[10];
    const float* dbih = (const float*)d_in[11];
    const float* dbhh = (const float*)d_in[12];
    const float* fclw = (const float*)d_in[13];
    const float* fclb = (const float*)d_in[14];
    float* out = (float*)d_out;

    zero_flags_kernel<<<8, 256>>>();
    conv_front_kernel<<<1, 256>>>(X, c1w, c1b, c2w, c2b);
    pack_weights_kernel<<<4 * 256 * 48, 256>>>(eih, ehh, dih, dhh);
    gru_wave_kernel<<<8 * NLAY, 192>>>(ebih, ebhh, dbih, dbhh);
    attn_fc_kernel<<<TSTEPS, 256>>>(fclw, fclb, out);
}